// round 16
// baseline (speedup 1.0000x reference)
#include <cuda_runtime.h>
#include <cuda_bf16.h>
#include <mma.h>
#include <cstdint>

using namespace nvcuda;

#define BB 4
#define CC 128
#define NN 4096
#define LDH 136   // bf16 tile leading dim (pad 8)
#define LDF 132   // fp32 tile leading dim (pad 4)
#define LDC 68    // fp32 col-major C leading dim (64+4)

typedef wmma::fragment<wmma::matrix_a,16,16,16,__nv_bfloat16,wmma::row_major> FragA;
typedef wmma::fragment<wmma::matrix_b,16,16,16,__nv_bfloat16,wmma::col_major> FragBc;
typedef wmma::fragment<wmma::accumulator,16,16,16,float> FragC;

// ---------------- device scratch ----------------
__device__ __align__(16) __nv_bfloat16 d_wqkv[3*CC*CC];
__device__ __align__(16) __nv_bfloat16 d_wproj[CC*CC];
__device__ float d_scl[BB*CC];
__device__ float d_sht[BB*CC];
__device__ __align__(16) uint8_t d_q[BB*NN*CC];         // [b][n][c] e4m3, x4 scale
__device__ __align__(16) uint8_t d_k[BB*NN*CC];         // [b][n][c] e4m3, x4 scale
__device__ __align__(16) __nv_bfloat16 d_v[BB*NN*CC];   // [b][n][c]
__device__ __align__(16) float d_op[2*BB*NN*CC];        // kv-split partial O (fp32)
__device__ float d_l[2*BB*NN];                          // kv-split partial row sums

// ================= low-level helpers =================
__device__ __forceinline__ uint32_t smem_u32(const void* p) {
    uint32_t a;
    asm("{ .reg .u64 t; cvta.to.shared.u64 t, %1; cvt.u32.u64 %0, t; }" : "=r"(a) : "l"(p));
    return a;
}
__device__ __forceinline__ void cpa16(uint32_t d, const void* s) {
    asm volatile("cp.async.cg.shared.global [%0], [%1], 16;" :: "r"(d), "l"(s));
}
#define CP_COMMIT() asm volatile("cp.async.commit_group;" ::: "memory")
#define CP_WAIT(n)  asm volatile("cp.async.wait_group %0;" :: "n"(n) : "memory")

__device__ __forceinline__ void ldsm4(uint32_t r[4], uint32_t a) {
    asm volatile("ldmatrix.sync.aligned.m8n8.x4.shared.b16 {%0,%1,%2,%3}, [%4];"
        : "=r"(r[0]), "=r"(r[1]), "=r"(r[2]), "=r"(r[3]) : "r"(a));
}
__device__ __forceinline__ void ldsm4t(uint32_t r[4], uint32_t a) {
    asm volatile("ldmatrix.sync.aligned.m8n8.x4.trans.shared.b16 {%0,%1,%2,%3}, [%4];"
        : "=r"(r[0]), "=r"(r[1]), "=r"(r[2]), "=r"(r[3]) : "r"(a));
}
__device__ __forceinline__ void mma16816(float c[4], const uint32_t a[4], const uint32_t b[2]) {
    asm volatile("mma.sync.aligned.m16n8k16.row.col.f32.bf16.bf16.f32 "
        "{%0,%1,%2,%3}, {%4,%5,%6,%7}, {%8,%9}, {%0,%1,%2,%3};"
        : "+f"(c[0]), "+f"(c[1]), "+f"(c[2]), "+f"(c[3])
        : "r"(a[0]), "r"(a[1]), "r"(a[2]), "r"(a[3]), "r"(b[0]), "r"(b[1]));
}
__device__ __forceinline__ void mma16832f8(float c[4], const uint32_t a[4], const uint32_t b[2]) {
    asm volatile("mma.sync.aligned.m16n8k32.row.col.f32.e4m3.e4m3.f32 "
        "{%0,%1,%2,%3}, {%4,%5,%6,%7}, {%8,%9}, {%0,%1,%2,%3};"
        : "+f"(c[0]), "+f"(c[1]), "+f"(c[2]), "+f"(c[3])
        : "r"(a[0]), "r"(a[1]), "r"(a[2]), "r"(a[3]), "r"(b[0]), "r"(b[1]));
}
__device__ __forceinline__ float ex2f(float x) {
    float y;
    asm("ex2.approx.f32 %0, %1;" : "=f"(y) : "f"(x));
    return y;
}
__device__ __forceinline__ uint32_t packbf2(float a, float b) {
    __nv_bfloat162 h = __floats2bfloat162_rn(a, b);
    return *(uint32_t*)&h;
}
// pack 4 floats to 4 e4m3 bytes (f0 -> lowest byte)
__device__ __forceinline__ uint32_t pk4e4(float f0, float f1, float f2, float f3) {
    unsigned short lo, hi;
    asm("cvt.rn.satfinite.e4m3x2.f32 %0, %1, %2;" : "=h"(lo) : "f"(f1), "f"(f0));
    asm("cvt.rn.satfinite.e4m3x2.f32 %0, %1, %2;" : "=h"(hi) : "f"(f3), "f"(f2));
    return (uint32_t)lo | ((uint32_t)hi << 16);
}

// ---------------- K0+K1 merged: weight convert + GroupNorm stats ----------------
__global__ __launch_bounds__(256) void k_prep(const float* __restrict__ x,
                                              const float* __restrict__ nw,
                                              const float* __restrict__ nb,
                                              const float* __restrict__ qkvw,
                                              const float* __restrict__ projw) {
    __shared__ float rs[8], rs2[8];
    __shared__ float smean, srstd;
    if (blockIdx.x < 192) {
        int i = blockIdx.x*256 + threadIdx.x;
        if (i < 3*CC*CC) d_wqkv[i]  = __float2bfloat16(qkvw[i]);
        if (i < CC*CC)   d_wproj[i] = __float2bfloat16(projw[i]);
        return;
    }
    int bg = blockIdx.x - 192;
    int b = bg >> 3, g = bg & 7;
    const float4* p = (const float4*)(x + ((size_t)(b*CC) + g*16)*NN);
    const int M4 = (16*NN)/4;
    float s = 0.f, s2 = 0.f;
    for (int i = threadIdx.x; i < M4; i += 256) {
        float4 v = p[i];
        s  += v.x + v.y + v.z + v.w;
        s2 += v.x*v.x + v.y*v.y + v.z*v.z + v.w*v.w;
    }
    #pragma unroll
    for (int o = 16; o; o >>= 1) {
        s  += __shfl_xor_sync(0xffffffffu, s,  o);
        s2 += __shfl_xor_sync(0xffffffffu, s2, o);
    }
    if ((threadIdx.x & 31) == 0) { rs[threadIdx.x>>5] = s; rs2[threadIdx.x>>5] = s2; }
    __syncthreads();
    if (threadIdx.x == 0) {
        float ts = 0.f, ts2 = 0.f;
        #pragma unroll
        for (int i = 0; i < 8; i++) { ts += rs[i]; ts2 += rs2[i]; }
        const float M = 16.f*NN;
        float mean = ts / M;
        float var  = ts2 / M - mean*mean;
        smean = mean;
        srstd = rsqrtf(var + 1e-5f);
    }
    __syncthreads();
    if (threadIdx.x < 16) {
        int c = g*16 + threadIdx.x;
        float w = nw[c];
        d_scl[b*CC + c] = srstd * w;
        d_sht[b*CC + c] = nb[c] - smean * srstd * w;
    }
}

// ---------------- K2: fused normalize + QKV GEMM, M-tile 64, 2 CTA/SM ----------------
// q,k written as e4m3 scaled x4; v written bf16.
__global__ __launch_bounds__(256) void k_qkv(const float* __restrict__ x,
                                             const float* __restrict__ qkvb) {
    extern __shared__ char sm[];
    __nv_bfloat16* As = (__nv_bfloat16*)sm;                 // [64][LDH]
    __nv_bfloat16* Bs = As + 64*LDH;                        // [128][LDH]
    float*         Cs = (float*)(Bs + 128*LDH);             // [64][LDF]
    const int nt = blockIdx.x, b = blockIdx.y, tid = threadIdx.x;
    const int nbase = nt*64;

    {
        int c = tid >> 1, nh = tid & 1;
        const float4* xp = (const float4*)(x + ((size_t)(b*CC) + c)*NN + nbase + nh*32);
        float sc = d_scl[b*CC + c], sh = d_sht[b*CC + c];
        #pragma unroll
        for (int i = 0; i < 8; i++) {
            float4 v = xp[i];
            int n = nh*32 + i*4;
            As[(n+0)*LDH + c] = __float2bfloat16(v.x*sc + sh);
            As[(n+1)*LDH + c] = __float2bfloat16(v.y*sc + sh);
            As[(n+2)*LDH + c] = __float2bfloat16(v.z*sc + sh);
            As[(n+3)*LDH + c] = __float2bfloat16(v.w*sc + sh);
        }
    }

    const int w = tid >> 5, wr = w >> 2, wc = w & 3;
    for (int ot = 0; ot < 3; ot++) {
        __syncthreads();
        {
            int o = tid >> 1, ch = tid & 1;
            const uint2* wp = (const uint2*)(d_wqkv + (ot*128 + o)*CC + ch*64);
            uint2* dp = (uint2*)(Bs + o*LDH + ch*64);
            #pragma unroll
            for (int i = 0; i < 16; i++) dp[i] = wp[i];
        }
        __syncthreads();
        #pragma unroll
        for (int i = 0; i < 2; i++) {
            FragC acc[2];
            #pragma unroll
            for (int jj = 0; jj < 2; jj++) wmma::fill_fragment(acc[jj], 0.f);
            #pragma unroll
            for (int k = 0; k < 8; k++) {
                FragA a; wmma::load_matrix_sync(a, As + (wr*32 + i*16)*LDH + k*16, LDH);
                #pragma unroll
                for (int jj = 0; jj < 2; jj++) {
                    FragBc bfr; wmma::load_matrix_sync(bfr, Bs + (wc*32 + jj*16)*LDH + k*16, LDH);
                    wmma::mma_sync(acc[jj], a, bfr, acc[jj]);
                }
            }
            #pragma unroll
            for (int jj = 0; jj < 2; jj++)
                wmma::store_matrix_sync(Cs + (wr*32 + i*16)*LDF + wc*32 + jj*16, acc[jj], LDF, wmma::mem_row_major);
        }
        __syncthreads();
        if (ot < 2) {
            // q/k: e4m3 with x4 scale
            uint8_t* dst = (ot == 0) ? d_q : d_k;
            int n = tid >> 2, oh = tid & 3;
            uint8_t* op = dst + ((size_t)(b*NN) + nbase + n)*CC + oh*32;
            const float* cp = Cs + n*LDF + oh*32;
            const float* bp = qkvb + ot*128 + oh*32;
            uint32_t wv[8];
            #pragma unroll
            for (int i = 0; i < 8; i++)
                wv[i] = pk4e4((cp[4*i+0] + bp[4*i+0])*4.f, (cp[4*i+1] + bp[4*i+1])*4.f,
                              (cp[4*i+2] + bp[4*i+2])*4.f, (cp[4*i+3] + bp[4*i+3])*4.f);
            *(uint4*)op        = make_uint4(wv[0], wv[1], wv[2], wv[3]);
            *(uint4*)(op + 16) = make_uint4(wv[4], wv[5], wv[6], wv[7]);
        } else {
            // v: bf16
            int n = tid >> 2, oh = tid & 3;
            __nv_bfloat16* op = d_v + ((size_t)(b*NN) + nbase + n)*CC + oh*32;
            const float4* cp = (const float4*)(Cs + n*LDF + oh*32);
            const float4* bp = (const float4*)(qkvb + 256 + oh*32);
            #pragma unroll
            for (int g2 = 0; g2 < 4; g2++) {
                float4 a = cp[2*g2], c2 = cp[2*g2+1];
                float4 b0 = bp[2*g2], b1 = bp[2*g2+1];
                uint4 wv;
                wv.x = packbf2(a.x + b0.x,  a.y + b0.y);
                wv.y = packbf2(a.z + b0.z,  a.w + b0.w);
                wv.z = packbf2(c2.x + b1.x, c2.y + b1.y);
                wv.w = packbf2(c2.z + b1.z, c2.w + b1.w);
                *(uint4*)(op + 8*g2) = wv;
            }
        }
    }
}

// ---------------- K3: attention — FA2, fp8 QK^T + bf16 PV ----------------
// CTA: 256 thr (8 warps), q-tile 256 (32 rows/warp), kv-tile 128, kv-split 2.
// smem: sQ(fp8) 32KB | sK0,sK1(fp8) 16KB | sV0,sV1(bf16) 32KB = 128KB.

__device__ __forceinline__ void load_ktile_f8(uint32_t sbase, const uint8_t* g, int tid) {
    // 128 rows x 128B; 1024 chunks, 4/thread
    #pragma unroll
    for (int j = 0; j < 4; j++) {
        int id = tid + 256*j;
        int row = id >> 3, c = id & 7;
        cpa16(sbase + row*128 + ((c ^ (row & 7)) << 4), g + row*CC + c*16);
    }
}
__device__ __forceinline__ void load_vtile(uint32_t sbase, const __nv_bfloat16* g, int tid) {
    // 128 rows x 256B; 2048 chunks, 8/thread
    #pragma unroll
    for (int j = 0; j < 8; j++) {
        int id = tid + 256*j;
        int row = id >> 4, c = id & 15;
        cpa16(sbase + row*256 + ((c ^ (row & 7)) << 4), g + row*CC + c*8);
    }
}

__device__ __forceinline__ void compute_S_f8(uint32_t sKb, int s, int lane,
                                             const uint32_t qf[2][4][4],
                                             float sc[2][2][4]) {
    const int r8 = lane & 7;
    #pragma unroll
    for (int rf = 0; rf < 2; rf++)
        #pragma unroll
        for (int nh = 0; nh < 2; nh++)
            #pragma unroll
            for (int e = 0; e < 4; e++) sc[rf][nh][e] = 0.f;
    #pragma unroll
    for (int kb = 0; kb < 4; kb++) {
        uint32_t kf[4];
        // x4 tiles: (ngrp0,klo),(ngrp0,khi),(ngrp1,klo),(ngrp1,khi)
        int nrow = s*16 + (lane >> 4)*8 + r8;
        int ch = 2*kb + ((lane >> 3) & 1);
        ldsm4(kf, sKb + nrow*128 + ((ch ^ r8) << 4));
        #pragma unroll
        for (int rf = 0; rf < 2; rf++) {
            mma16832f8(sc[rf][0], qf[rf][kb], kf);
            mma16832f8(sc[rf][1], qf[rf][kb], kf + 2);
        }
    }
}

__device__ __forceinline__ void compute_PV(uint32_t sVb, int s, int lane,
                                           const uint32_t pk[2][4],
                                           float o[2][16][4]) {
    const int r8 = lane & 7, hs = (lane >> 3) & 1, q16 = lane >> 4;
    #pragma unroll
    for (int cf = 0; cf < 8; cf++) {
        uint32_t vf[4];
        int ch = 2*cf + q16;
        ldsm4t(vf, sVb + (s*16 + hs*8 + r8)*256 + ((ch ^ r8) << 4));
        #pragma unroll
        for (int rf = 0; rf < 2; rf++) {
            mma16816(o[rf][2*cf],     pk[rf], vf);
            mma16816(o[rf][2*cf + 1], pk[rf], vf + 2);
        }
    }
}

__global__ __launch_bounds__(256) void k_attn() {
    extern __shared__ char sm[];
    const int tid = threadIdx.x, lane = tid & 31, w = tid >> 5;
    const int qt = blockIdx.x, ks = blockIdx.y, b = blockIdx.z;
    const uint32_t sb = smem_u32(sm);
    const uint32_t sQ = sb;
    const uint32_t sK[2] = { sb + 32768, sb + 49152 };
    const uint32_t sV[2] = { sb + 65536, sb + 98304 };

    const uint8_t* gq = d_q + ((size_t)(b*NN) + qt*256)*CC;
    const uint8_t* gk = d_k + ((size_t)(b*NN) + ks*2048)*CC;
    const __nv_bfloat16* gv = d_v + ((size_t)(b*NN) + ks*2048)*CC;

    // ---- prologue: Q (256 rows x 128B fp8) + kv tiles 0,1 ----
    #pragma unroll
    for (int j = 0; j < 8; j++) {
        int id = tid + 256*j;
        int row = id >> 3, c = id & 7;
        cpa16(sQ + row*128 + ((c ^ (row & 7)) << 4), gq + row*CC + c*16);
    }
    load_ktile_f8(sK[0], gk, tid);
    load_vtile(sV[0], gv, tid);
    CP_COMMIT();
    load_ktile_f8(sK[1], gk + (size_t)128*CC, tid);
    load_vtile(sV[1], gv + (size_t)128*CC, tid);
    CP_COMMIT();

    const int r8 = lane & 7;
    const int hs = (lane >> 3) & 1;
    const int q16 = lane >> 4;

    CP_WAIT(1);
    __syncthreads();

    // ---- Q fragments (fp8 A-operand): 2 row-frags x 4 k-frags (k=32 each) ----
    uint32_t qf[2][4][4];
    #pragma unroll
    for (int rf = 0; rf < 2; rf++)
        #pragma unroll
        for (int kb = 0; kb < 4; kb++) {
            int row = w*32 + rf*16 + hs*8 + r8;
            int ch = 2*kb + q16;
            ldsm4(qf[rf][kb], sQ + row*128 + ((ch ^ r8) << 4));
        }

    float o[2][16][4];
    #pragma unroll
    for (int rf = 0; rf < 2; rf++)
        #pragma unroll
        for (int cf = 0; cf < 16; cf++)
            #pragma unroll
            for (int e = 0; e < 4; e++) o[rf][cf][e] = 0.f;
    float l[2][2] = {{0.f, 0.f}, {0.f, 0.f}};
    // (1/sqrt(128)) * log2(e) / 16  (q,k each stored x4)
    const float sl2e = 0.0079698400f;

    #pragma unroll 1
    for (int it = 0; it < 16; it++) {
        const int bi = it & 1;
        if (it > 0) { CP_WAIT(1); __syncthreads(); }

        float sc[2][2][4];
        compute_S_f8(sK[bi], 0, lane, qf, sc);

        #pragma unroll
        for (int s = 0; s < 8; s++) {
            uint32_t pk[2][4];
            #pragma unroll
            for (int rf = 0; rf < 2; rf++) {
                #pragma unroll
                for (int nh = 0; nh < 2; nh++)
                    #pragma unroll
                    for (int e = 0; e < 4; e++)
                        sc[rf][nh][e] = ex2f(sc[rf][nh][e]*sl2e);
                l[rf][0] += sc[rf][0][0] + sc[rf][0][1] + sc[rf][1][0] + sc[rf][1][1];
                l[rf][1] += sc[rf][0][2] + sc[rf][0][3] + sc[rf][1][2] + sc[rf][1][3];
                pk[rf][0] = packbf2(sc[rf][0][0], sc[rf][0][1]);
                pk[rf][1] = packbf2(sc[rf][0][2], sc[rf][0][3]);
                pk[rf][2] = packbf2(sc[rf][1][0], sc[rf][1][1]);
                pk[rf][3] = packbf2(sc[rf][1][2], sc[rf][1][3]);
            }
            if (s < 7) compute_S_f8(sK[bi], s + 1, lane, qf, sc);
            compute_PV(sV[bi], s, lane, pk, o);
        }

        __syncthreads();
        if (it + 2 < 16) {
            load_ktile_f8(sK[bi], gk + (size_t)(it + 2)*128*CC, tid);
            load_vtile(sV[bi], gv + (size_t)(it + 2)*128*CC, tid);
        }
        CP_COMMIT();
    }

    // ---- epilogue: write unnormalized fp32 partial O + partial l ----
    const int grp = lane >> 2, tc = lane & 3;
    float* op = d_op + (((size_t)ks*BB + b)*NN + qt*256 + w*32)*CC;
    #pragma unroll
    for (int rf = 0; rf < 2; rf++)
        #pragma unroll
        for (int cf = 0; cf < 16; cf++) {
            int col = cf*8 + 2*tc;
            *(float2*)(op + (rf*16 + grp    )*CC + col) = make_float2(o[rf][cf][0], o[rf][cf][1]);
            *(float2*)(op + (rf*16 + grp + 8)*CC + col) = make_float2(o[rf][cf][2], o[rf][cf][3]);
        }
    #pragma unroll
    for (int rf = 0; rf < 2; rf++)
        #pragma unroll
        for (int h = 0; h < 2; h++) {
            float v = l[rf][h];
            v += __shfl_xor_sync(0xffffffffu, v, 1);
            v += __shfl_xor_sync(0xffffffffu, v, 2);
            if (tc == 0)
                d_l[((size_t)ks*BB + b)*NN + qt*256 + w*32 + rf*16 + grp + 8*h] = v;
        }
}

// ---------------- K4: combine + proj GEMM + residual, M-tile 64, 2 CTA/SM ----------------
__global__ __launch_bounds__(256) void k_proj(const float* __restrict__ x,
                                              const float* __restrict__ projb,
                                              float* __restrict__ out) {
    extern __shared__ char sm[];
    __nv_bfloat16* As = (__nv_bfloat16*)sm;                 // [64][LDH]
    __nv_bfloat16* Bs = As + 64*LDH;                        // [128][LDH]
    float*         Cs = (float*)(Bs + 128*LDH);             // [128][LDC] col-major
    const int nt = blockIdx.x, b = blockIdx.y, tid = threadIdx.x;
    const int nbase = nt*64;

    {
        int n = tid >> 2, hh = tid & 3;
        size_t base = ((size_t)(b*NN) + nbase + n)*CC + hh*32;
        const float4* p0 = (const float4*)(d_op + base);
        const float4* p1 = (const float4*)(d_op + (size_t)BB*NN*CC + base);
        float inv = 1.f / (d_l[(size_t)b*NN + nbase + n] +
                           d_l[(size_t)BB*NN + b*NN + nbase + n]);
        uint32_t* ap = (uint32_t*)(As + n*LDH + hh*32);
        #pragma unroll
        for (int i = 0; i < 8; i++) {
            float4 a = p0[i], c = p1[i];
            ap[2*i]   = packbf2((a.x + c.x)*inv, (a.y + c.y)*inv);
            ap[2*i+1] = packbf2((a.z + c.z)*inv, (a.w + c.w)*inv);
        }
    }
    {
        int o = tid >> 1, ch = tid & 1;
        const uint2* wp = (const uint2*)(d_wproj + o*CC + ch*64);
        uint2* dp = (uint2*)(Bs + o*LDH + ch*64);
        #pragma unroll
        for (int i = 0; i < 16; i++) dp[i] = wp[i];
    }
    __syncthreads();

    const int w = tid >> 5, wr = w >> 2, wc = w & 3;
    #pragma unroll
    for (int i = 0; i < 2; i++) {
        FragC acc[2];
        #pragma unroll
        for (int jj = 0; jj < 2; jj++) wmma::fill_fragment(acc[jj], 0.f);
        #pragma unroll
        for (int k = 0; k < 8; k++) {
            FragA a; wmma::load_matrix_sync(a, As + (wr*32 + i*16)*LDH + k*16, LDH);
            #pragma unroll
            for (int jj = 0; jj < 2; jj++) {
                FragBc bfr; wmma::load_matrix_sync(bfr, Bs + (wc*32 + jj*16)*LDH + k*16, LDH);
                wmma::mma_sync(acc[jj], a, bfr, acc[jj]);
            }
        }
        #pragma unroll
        for (int jj = 0; jj < 2; jj++)
            wmma::store_matrix_sync(Cs + (wc*32 + jj*16)*LDC + wr*32 + i*16, acc[jj], LDC, wmma::mem_col_major);
    }
    __syncthreads();
    {
        int c = tid >> 1, nh = tid & 1;
        const float4* xp = (const float4*)(x + ((size_t)(b*CC) + c)*NN + nbase + nh*32);
        float4* op = (float4*)(out + ((size_t)(b*CC) + c)*NN + nbase + nh*32);
        const float4* cp = (const float4*)(Cs + c*LDC + nh*32);
        float pb = projb[c];
        #pragma unroll
        for (int i = 0; i < 8; i++) {
            float4 xv = xp[i], cv = cp[i];
            op[i] = make_float4(xv.x + pb + cv.x, xv.y + pb + cv.y,
                                xv.z + pb + cv.z, xv.w + pb + cv.w);
        }
    }
}

// ---------------- launcher ----------------
extern "C" void kernel_launch(void* const* d_in, const int* in_sizes, int n_in,
                              void* d_out, int out_size) {
    const float* x     = (const float*)d_in[0];
    const float* nw    = (const float*)d_in[1];
    const float* nb    = (const float*)d_in[2];
    const float* qkvw  = (const float*)d_in[3];
    const float* qkvb  = (const float*)d_in[4];
    const float* projw = (const float*)d_in[5];
    const float* projb = (const float*)d_in[6];
    float* out = (float*)d_out;

    const int SM_QKV  = 64*LDH*2 + 128*LDH*2 + 64*LDF*4;   // 86016
    const int SM_PROJ = 64*LDH*2 + 128*LDH*2 + 128*LDC*4;  // 87040
    const int SM_ATTN = 32768 + 2*16384 + 2*32768;         // 131072

    cudaFuncSetAttribute(k_qkv,  cudaFuncAttributeMaxDynamicSharedMemorySize, SM_QKV);
    cudaFuncSetAttribute(k_attn, cudaFuncAttributeMaxDynamicSharedMemorySize, SM_ATTN);
    cudaFuncSetAttribute(k_proj, cudaFuncAttributeMaxDynamicSharedMemorySize, SM_PROJ);

    k_prep<<<224, 256>>>(x, nw, nb, qkvw, projw);
    k_qkv<<<dim3(64, BB), 256, SM_QKV>>>(x, qkvb);
    k_attn<<<dim3(16, 2, BB), 256, SM_ATTN>>>();
    k_proj<<<dim3(64, BB), 256, SM_PROJ>>>(x, projb, out);
}

// round 17
// speedup vs baseline: 1.1364x; 1.1364x over previous
#include <cuda_runtime.h>
#include <cuda_bf16.h>
#include <cuda_fp16.h>
#include <mma.h>
#include <cstdint>

using namespace nvcuda;

#define BB 4
#define CC 128
#define NN 4096
#define LDH 136   // bf16 tile leading dim (pad 8)
#define LDF 132   // fp32 tile leading dim (pad 4)
#define LDC 68    // fp32 col-major C leading dim (64+4)

typedef wmma::fragment<wmma::matrix_a,16,16,16,__nv_bfloat16,wmma::row_major> FragA;
typedef wmma::fragment<wmma::matrix_b,16,16,16,__nv_bfloat16,wmma::col_major> FragBc;
typedef wmma::fragment<wmma::accumulator,16,16,16,float> FragC;

// ---------------- device scratch ----------------
__device__ __align__(16) __nv_bfloat16 d_wqkv[3*CC*CC];
__device__ __align__(16) __nv_bfloat16 d_wproj[CC*CC];
__device__ float d_scl[BB*CC];
__device__ float d_sht[BB*CC];
__device__ __align__(16) __nv_bfloat16 d_q[BB*NN*CC];   // [b][n][c]
__device__ __align__(16) __nv_bfloat16 d_k[BB*NN*CC];   // [b][n][c]
__device__ __align__(16) __half d_v[BB*NN*CC];          // [b][n][c] f16
__device__ __align__(16) float d_op[2*BB*NN*CC];        // kv-split partial O (fp32)
__device__ float d_l[2*BB*NN];                          // kv-split partial row sums

// ================= low-level helpers =================
__device__ __forceinline__ uint32_t smem_u32(const void* p) {
    uint32_t a;
    asm("{ .reg .u64 t; cvta.to.shared.u64 t, %1; cvt.u32.u64 %0, t; }" : "=r"(a) : "l"(p));
    return a;
}
__device__ __forceinline__ void cpa16(uint32_t d, const void* s) {
    asm volatile("cp.async.cg.shared.global [%0], [%1], 16;" :: "r"(d), "l"(s));
}
#define CP_COMMIT() asm volatile("cp.async.commit_group;" ::: "memory")
#define CP_WAIT(n)  asm volatile("cp.async.wait_group %0;" :: "n"(n) : "memory")

__device__ __forceinline__ void ldsm4(uint32_t r[4], uint32_t a) {
    asm volatile("ldmatrix.sync.aligned.m8n8.x4.shared.b16 {%0,%1,%2,%3}, [%4];"
        : "=r"(r[0]), "=r"(r[1]), "=r"(r[2]), "=r"(r[3]) : "r"(a));
}
__device__ __forceinline__ void ldsm4t(uint32_t r[4], uint32_t a) {
    asm volatile("ldmatrix.sync.aligned.m8n8.x4.trans.shared.b16 {%0,%1,%2,%3}, [%4];"
        : "=r"(r[0]), "=r"(r[1]), "=r"(r[2]), "=r"(r[3]) : "r"(a));
}
__device__ __forceinline__ void mma16816(float c[4], const uint32_t a[4], const uint32_t b[2]) {
    asm volatile("mma.sync.aligned.m16n8k16.row.col.f32.bf16.bf16.f32 "
        "{%0,%1,%2,%3}, {%4,%5,%6,%7}, {%8,%9}, {%0,%1,%2,%3};"
        : "+f"(c[0]), "+f"(c[1]), "+f"(c[2]), "+f"(c[3])
        : "r"(a[0]), "r"(a[1]), "r"(a[2]), "r"(a[3]), "r"(b[0]), "r"(b[1]));
}
// f16 x f16 -> f16 accumulate (halves accumulator register footprint)
__device__ __forceinline__ void mma16816h(uint32_t c[2], const uint32_t a[4], const uint32_t b[2]) {
    asm volatile("mma.sync.aligned.m16n8k16.row.col.f16.f16.f16.f16 "
        "{%0,%1}, {%2,%3,%4,%5}, {%6,%7}, {%0,%1};"
        : "+r"(c[0]), "+r"(c[1])
        : "r"(a[0]), "r"(a[1]), "r"(a[2]), "r"(a[3]), "r"(b[0]), "r"(b[1]));
}
__device__ __forceinline__ float ex2f(float x) {
    float y;
    asm("ex2.approx.f32 %0, %1;" : "=f"(y) : "f"(x));
    return y;
}
__device__ __forceinline__ uint32_t packbf2(float a, float b) {
    __nv_bfloat162 h = __floats2bfloat162_rn(a, b);
    return *(uint32_t*)&h;
}
__device__ __forceinline__ uint32_t packh2(float a, float b) {
    __half2 h = __floats2half2_rn(a, b);
    return *(uint32_t*)&h;
}

// ---------------- K0+K1 merged: weight convert + GroupNorm stats ----------------
__global__ __launch_bounds__(256) void k_prep(const float* __restrict__ x,
                                              const float* __restrict__ nw,
                                              const float* __restrict__ nb,
                                              const float* __restrict__ qkvw,
                                              const float* __restrict__ projw) {
    __shared__ float rs[8], rs2[8];
    __shared__ float smean, srstd;
    if (blockIdx.x < 192) {
        int i = blockIdx.x*256 + threadIdx.x;
        if (i < 3*CC*CC) d_wqkv[i]  = __float2bfloat16(qkvw[i]);
        if (i < CC*CC)   d_wproj[i] = __float2bfloat16(projw[i]);
        return;
    }
    int bg = blockIdx.x - 192;
    int b = bg >> 3, g = bg & 7;
    const float4* p = (const float4*)(x + ((size_t)(b*CC) + g*16)*NN);
    const int M4 = (16*NN)/4;
    float s = 0.f, s2 = 0.f;
    for (int i = threadIdx.x; i < M4; i += 256) {
        float4 v = p[i];
        s  += v.x + v.y + v.z + v.w;
        s2 += v.x*v.x + v.y*v.y + v.z*v.z + v.w*v.w;
    }
    #pragma unroll
    for (int o = 16; o; o >>= 1) {
        s  += __shfl_xor_sync(0xffffffffu, s,  o);
        s2 += __shfl_xor_sync(0xffffffffu, s2, o);
    }
    if ((threadIdx.x & 31) == 0) { rs[threadIdx.x>>5] = s; rs2[threadIdx.x>>5] = s2; }
    __syncthreads();
    if (threadIdx.x == 0) {
        float ts = 0.f, ts2 = 0.f;
        #pragma unroll
        for (int i = 0; i < 8; i++) { ts += rs[i]; ts2 += rs2[i]; }
        const float M = 16.f*NN;
        float mean = ts / M;
        float var  = ts2 / M - mean*mean;
        smean = mean;
        srstd = rsqrtf(var + 1e-5f);
    }
    __syncthreads();
    if (threadIdx.x < 16) {
        int c = g*16 + threadIdx.x;
        float w = nw[c];
        d_scl[b*CC + c] = srstd * w;
        d_sht[b*CC + c] = nb[c] - smean * srstd * w;
    }
}

// ---------------- K2: fused normalize + QKV GEMM, M-tile 64, 2 CTA/SM ----------------
__global__ __launch_bounds__(256) void k_qkv(const float* __restrict__ x,
                                             const float* __restrict__ qkvb) {
    extern __shared__ char sm[];
    __nv_bfloat16* As = (__nv_bfloat16*)sm;                 // [64][LDH]
    __nv_bfloat16* Bs = As + 64*LDH;                        // [128][LDH]
    float*         Cs = (float*)(Bs + 128*LDH);             // [64][LDF]
    const int nt = blockIdx.x, b = blockIdx.y, tid = threadIdx.x;
    const int nbase = nt*64;

    {
        int c = tid >> 1, nh = tid & 1;
        const float4* xp = (const float4*)(x + ((size_t)(b*CC) + c)*NN + nbase + nh*32);
        float sc = d_scl[b*CC + c], sh = d_sht[b*CC + c];
        #pragma unroll
        for (int i = 0; i < 8; i++) {
            float4 v = xp[i];
            int n = nh*32 + i*4;
            As[(n+0)*LDH + c] = __float2bfloat16(v.x*sc + sh);
            As[(n+1)*LDH + c] = __float2bfloat16(v.y*sc + sh);
            As[(n+2)*LDH + c] = __float2bfloat16(v.z*sc + sh);
            As[(n+3)*LDH + c] = __float2bfloat16(v.w*sc + sh);
        }
    }

    const int w = tid >> 5, wr = w >> 2, wc = w & 3;
    for (int ot = 0; ot < 3; ot++) {
        __syncthreads();
        {
            int o = tid >> 1, ch = tid & 1;
            const uint2* wp = (const uint2*)(d_wqkv + (ot*128 + o)*CC + ch*64);
            uint2* dp = (uint2*)(Bs + o*LDH + ch*64);
            #pragma unroll
            for (int i = 0; i < 16; i++) dp[i] = wp[i];
        }
        __syncthreads();
        #pragma unroll
        for (int i = 0; i < 2; i++) {
            FragC acc[2];
            #pragma unroll
            for (int jj = 0; jj < 2; jj++) wmma::fill_fragment(acc[jj], 0.f);
            #pragma unroll
            for (int k = 0; k < 8; k++) {
                FragA a; wmma::load_matrix_sync(a, As + (wr*32 + i*16)*LDH + k*16, LDH);
                #pragma unroll
                for (int jj = 0; jj < 2; jj++) {
                    FragBc bfr; wmma::load_matrix_sync(bfr, Bs + (wc*32 + jj*16)*LDH + k*16, LDH);
                    wmma::mma_sync(acc[jj], a, bfr, acc[jj]);
                }
            }
            #pragma unroll
            for (int jj = 0; jj < 2; jj++)
                wmma::store_matrix_sync(Cs + (wr*32 + i*16)*LDF + wc*32 + jj*16, acc[jj], LDF, wmma::mem_row_major);
        }
        __syncthreads();
        int n = tid >> 2, oh = tid & 3;
        const float4* cp = (const float4*)(Cs + n*LDF + oh*32);
        const float4* bp = (const float4*)(qkvb + ot*128 + oh*32);
        if (ot < 2) {
            // q, k: bf16
            __nv_bfloat16* op = ((ot == 0) ? d_q : d_k) + ((size_t)(b*NN) + nbase + n)*CC + oh*32;
            #pragma unroll
            for (int g2 = 0; g2 < 4; g2++) {
                float4 a = cp[2*g2], c2 = cp[2*g2+1];
                float4 b0 = bp[2*g2], b1 = bp[2*g2+1];
                uint4 wv;
                wv.x = packbf2(a.x + b0.x,  a.y + b0.y);
                wv.y = packbf2(a.z + b0.z,  a.w + b0.w);
                wv.z = packbf2(c2.x + b1.x, c2.y + b1.y);
                wv.w = packbf2(c2.z + b1.z, c2.w + b1.w);
                *(uint4*)(op + 8*g2) = wv;
            }
        } else {
            // v: f16 (PV path uses f16 accumulate mma)
            __half* op = d_v + ((size_t)(b*NN) + nbase + n)*CC + oh*32;
            #pragma unroll
            for (int g2 = 0; g2 < 4; g2++) {
                float4 a = cp[2*g2], c2 = cp[2*g2+1];
                float4 b0 = bp[2*g2], b1 = bp[2*g2+1];
                uint4 wv;
                wv.x = packh2(a.x + b0.x,  a.y + b0.y);
                wv.y = packh2(a.z + b0.z,  a.w + b0.w);
                wv.z = packh2(c2.x + b1.x, c2.y + b1.y);
                wv.w = packh2(c2.z + b1.z, c2.w + b1.w);
                *(uint4*)(op + 8*g2) = wv;
            }
        }
    }
}

// ---------------- K3: attention — register FA2, bf16 QK^T + f16-acc PV ----------------
// CTA: 256 thr (8 warps), q-tile 256 (32 rows/warp), kv-tile 128, kv-split 2.
// smem: sQ 64KB | sK0 32KB | sK1 32KB | sV0 32KB | sV1 32KB = 192KB.
// O accumulated in f16 (half2-packed): 64 regs instead of 128 -> scheduling headroom.

__device__ __forceinline__ void load_tile128(uint32_t sbase, const void* g, int tid) {
    #pragma unroll
    for (int j = 0; j < 8; j++) {
        int id = tid + 256*j;
        int row = id >> 4, c = id & 15;
        cpa16(sbase + row*256 + ((c ^ (row & 7)) << 4), (const char*)g + row*256 + c*16);
    }
}

__device__ __forceinline__ void compute_S(uint32_t sKb, int s, int lane,
                                          const uint32_t qf[2][8][4],
                                          float sc[2][2][4]) {
    const int r8 = lane & 7;
    #pragma unroll
    for (int rf = 0; rf < 2; rf++)
        #pragma unroll
        for (int nh = 0; nh < 2; nh++)
            #pragma unroll
            for (int e = 0; e < 4; e++) sc[rf][nh][e] = 0.f;
    #pragma unroll
    for (int kb2 = 0; kb2 < 4; kb2++) {
        uint32_t kf0[4], kf1[4];
        int ch = 4*kb2 + (lane >> 3);
        ldsm4(kf0, sKb + (s*16 +     r8)*256 + ((ch ^ r8) << 4));
        ldsm4(kf1, sKb + (s*16 + 8 + r8)*256 + ((ch ^ r8) << 4));
        #pragma unroll
        for (int rf = 0; rf < 2; rf++) {
            mma16816(sc[rf][0], qf[rf][2*kb2],     kf0);
            mma16816(sc[rf][0], qf[rf][2*kb2 + 1], kf0 + 2);
            mma16816(sc[rf][1], qf[rf][2*kb2],     kf1);
            mma16816(sc[rf][1], qf[rf][2*kb2 + 1], kf1 + 2);
        }
    }
}

__device__ __forceinline__ void compute_PV(uint32_t sVb, int s, int lane,
                                           const uint32_t pk[2][4],
                                           uint32_t o[2][16][2]) {
    const int r8 = lane & 7, hs = (lane >> 3) & 1, q16 = lane >> 4;
    #pragma unroll
    for (int cf = 0; cf < 8; cf++) {
        uint32_t vf[4];
        int ch = 2*cf + q16;
        ldsm4t(vf, sVb + (s*16 + hs*8 + r8)*256 + ((ch ^ r8) << 4));
        #pragma unroll
        for (int rf = 0; rf < 2; rf++) {
            mma16816h(o[rf][2*cf],     pk[rf], vf);
            mma16816h(o[rf][2*cf + 1], pk[rf], vf + 2);
        }
    }
}

__global__ __launch_bounds__(256) void k_attn() {
    extern __shared__ char sm[];
    const int tid = threadIdx.x, lane = tid & 31, w = tid >> 5;
    const int qt = blockIdx.x, ks = blockIdx.y, b = blockIdx.z;
    const uint32_t sb = smem_u32(sm);
    const uint32_t sQ = sb;
    const uint32_t sK[2] = { sb + 65536,  sb + 98304 };
    const uint32_t sV[2] = { sb + 131072, sb + 163840 };

    const __nv_bfloat16* gq = d_q + ((size_t)(b*NN) + qt*256)*CC;
    const __nv_bfloat16* gk = d_k + ((size_t)(b*NN) + ks*2048)*CC;
    const __half*        gv = d_v + ((size_t)(b*NN) + ks*2048)*CC;

    #pragma unroll
    for (int j = 0; j < 16; j++) {
        int id = tid + 256*j;
        int row = id >> 4, c = id & 15;
        cpa16(sQ + row*256 + ((c ^ (row & 7)) << 4), gq + row*CC + c*8);
    }
    load_tile128(sK[0], gk, tid);
    load_tile128(sV[0], gv, tid);
    CP_COMMIT();
    load_tile128(sK[1], gk + (size_t)128*CC, tid);
    load_tile128(sV[1], gv + (size_t)128*CC, tid);
    CP_COMMIT();

    const int r8 = lane & 7;
    const int hs = (lane >> 3) & 1;
    const int q16 = lane >> 4;

    CP_WAIT(1);
    __syncthreads();

    uint32_t qf[2][8][4];
    #pragma unroll
    for (int rf = 0; rf < 2; rf++)
        #pragma unroll
        for (int kb = 0; kb < 8; kb++) {
            int row = w*32 + rf*16 + hs*8 + r8;
            int ch = 2*kb + q16;
            ldsm4(qf[rf][kb], sQ + row*256 + ((ch ^ r8) << 4));
        }

    uint32_t o[2][16][2];
    #pragma unroll
    for (int rf = 0; rf < 2; rf++)
        #pragma unroll
        for (int cf = 0; cf < 16; cf++) {
            o[rf][cf][0] = 0u;
            o[rf][cf][1] = 0u;
        }
    float l[2][2] = {{0.f, 0.f}, {0.f, 0.f}};
    const float sl2e = 0.12751744f;     // (1/sqrt(128)) * log2(e)

    #pragma unroll 1
    for (int it = 0; it < 16; it++) {
        const int bi = it & 1;
        if (it > 0) { CP_WAIT(1); __syncthreads(); }

        float sc[2][2][4];
        compute_S(sK[bi], 0, lane, qf, sc);

        #pragma unroll
        for (int s = 0; s < 8; s++) {
            uint32_t pk[2][4];
            #pragma unroll
            for (int rf = 0; rf < 2; rf++) {
                #pragma unroll
                for (int nh = 0; nh < 2; nh++)
                    #pragma unroll
                    for (int e = 0; e < 4; e++)
                        sc[rf][nh][e] = ex2f(sc[rf][nh][e]*sl2e);
                l[rf][0] += sc[rf][0][0] + sc[rf][0][1] + sc[rf][1][0] + sc[rf][1][1];
                l[rf][1] += sc[rf][0][2] + sc[rf][0][3] + sc[rf][1][2] + sc[rf][1][3];
                pk[rf][0] = packh2(sc[rf][0][0], sc[rf][0][1]);
                pk[rf][1] = packh2(sc[rf][0][2], sc[rf][0][3]);
                pk[rf][2] = packh2(sc[rf][1][0], sc[rf][1][1]);
                pk[rf][3] = packh2(sc[rf][1][2], sc[rf][1][3]);
            }
            if (s < 7) compute_S(sK[bi], s + 1, lane, qf, sc);
            compute_PV(sV[bi], s, lane, pk, o);
        }

        __syncthreads();
        if (it + 2 < 16) {
            load_tile128(sK[bi], gk + (size_t)(it + 2)*128*CC, tid);
            load_tile128(sV[bi], gv + (size_t)(it + 2)*128*CC, tid);
        }
        CP_COMMIT();
    }

    // ---- epilogue: unpack f16 O, write unnormalized fp32 partials + l ----
    const int grp = lane >> 2, tc = lane & 3;
    float* op = d_op + (((size_t)ks*BB + b)*NN + qt*256 + w*32)*CC;
    #pragma unroll
    for (int rf = 0; rf < 2; rf++)
        #pragma unroll
        for (int cf = 0; cf < 16; cf++) {
            int col = cf*8 + 2*tc;
            float2 f0 = __half22float2(*(__half2*)&o[rf][cf][0]);
            float2 f1 = __half22float2(*(__half2*)&o[rf][cf][1]);
            *(float2*)(op + (rf*16 + grp    )*CC + col) = f0;
            *(float2*)(op + (rf*16 + grp + 8)*CC + col) = f1;
        }
    #pragma unroll
    for (int rf = 0; rf < 2; rf++)
        #pragma unroll
        for (int h = 0; h < 2; h++) {
            float v = l[rf][h];
            v += __shfl_xor_sync(0xffffffffu, v, 1);
            v += __shfl_xor_sync(0xffffffffu, v, 2);
            if (tc == 0)
                d_l[((size_t)ks*BB + b)*NN + qt*256 + w*32 + rf*16 + grp + 8*h] = v;
        }
}

// ---------------- K4: combine + proj GEMM + residual, M-tile 64, 2 CTA/SM ----------------
__global__ __launch_bounds__(256) void k_proj(const float* __restrict__ x,
                                              const float* __restrict__ projb,
                                              float* __restrict__ out) {
    extern __shared__ char sm[];
    __nv_bfloat16* As = (__nv_bfloat16*)sm;                 // [64][LDH]
    __nv_bfloat16* Bs = As + 64*LDH;                        // [128][LDH]
    float*         Cs = (float*)(Bs + 128*LDH);             // [128][LDC] col-major
    const int nt = blockIdx.x, b = blockIdx.y, tid = threadIdx.x;
    const int nbase = nt*64;

    {
        int n = tid >> 2, hh = tid & 3;
        size_t base = ((size_t)(b*NN) + nbase + n)*CC + hh*32;
        const float4* p0 = (const float4*)(d_op + base);
        const float4* p1 = (const float4*)(d_op + (size_t)BB*NN*CC + base);
        float inv = 1.f / (d_l[(size_t)b*NN + nbase + n] +
                           d_l[(size_t)BB*NN + b*NN + nbase + n]);
        uint32_t* ap = (uint32_t*)(As + n*LDH + hh*32);
        #pragma unroll
        for (int i = 0; i < 8; i++) {
            float4 a = p0[i], c = p1[i];
            ap[2*i]   = packbf2((a.x + c.x)*inv, (a.y + c.y)*inv);
            ap[2*i+1] = packbf2((a.z + c.z)*inv, (a.w + c.w)*inv);
        }
    }
    {
        int o = tid >> 1, ch = tid & 1;
        const uint2* wp = (const uint2*)(d_wproj + o*CC + ch*64);
        uint2* dp = (uint2*)(Bs + o*LDH + ch*64);
        #pragma unroll
        for (int i = 0; i < 16; i++) dp[i] = wp[i];
    }
    __syncthreads();

    const int w = tid >> 5, wr = w >> 2, wc = w & 3;
    #pragma unroll
    for (int i = 0; i < 2; i++) {
        FragC acc[2];
        #pragma unroll
        for (int jj = 0; jj < 2; jj++) wmma::fill_fragment(acc[jj], 0.f);
        #pragma unroll
        for (int k = 0; k < 8; k++) {
            FragA a; wmma::load_matrix_sync(a, As + (wr*32 + i*16)*LDH + k*16, LDH);
            #pragma unroll
            for (int jj = 0; jj < 2; jj++) {
                FragBc bfr; wmma::load_matrix_sync(bfr, Bs + (wc*32 + jj*16)*LDH + k*16, LDH);
                wmma::mma_sync(acc[jj], a, bfr, acc[jj]);
            }
        }
        #pragma unroll
        for (int jj = 0; jj < 2; jj++)
            wmma::store_matrix_sync(Cs + (wc*32 + jj*16)*LDC + wr*32 + i*16, acc[jj], LDC, wmma::mem_col_major);
    }
    __syncthreads();
    {
        int c = tid >> 1, nh = tid & 1;
        const float4* xp = (const float4*)(x + ((size_t)(b*CC) + c)*NN + nbase + nh*32);
        float4* op = (float4*)(out + ((size_t)(b*CC) + c)*NN + nbase + nh*32);
        const float4* cp = (const float4*)(Cs + c*LDC + nh*32);
        float pb = projb[c];
        #pragma unroll
        for (int i = 0; i < 8; i++) {
            float4 xv = xp[i], cv = cp[i];
            op[i] = make_float4(xv.x + pb + cv.x, xv.y + pb + cv.y,
                                xv.z + pb + cv.z, xv.w + pb + cv.w);
        }
    }
}

// ---------------- launcher ----------------
extern "C" void kernel_launch(void* const* d_in, const int* in_sizes, int n_in,
                              void* d_out, int out_size) {
    const float* x     = (const float*)d_in[0];
    const float* nw    = (const float*)d_in[1];
    const float* nb    = (const float*)d_in[2];
    const float* qkvw  = (const float*)d_in[3];
    const float* qkvb  = (const float*)d_in[4];
    const float* projw = (const float*)d_in[5];
    const float* projb = (const float*)d_in[6];
    float* out = (float*)d_out;

    const int SM_QKV  = 64*LDH*2 + 128*LDH*2 + 64*LDF*4;   // 86016
    const int SM_PROJ = 64*LDH*2 + 128*LDH*2 + 128*LDC*4;  // 87040
    const int SM_ATTN = 65536 + 4*32768;                   // 196608

    cudaFuncSetAttribute(k_qkv,  cudaFuncAttributeMaxDynamicSharedMemorySize, SM_QKV);
    cudaFuncSetAttribute(k_attn, cudaFuncAttributeMaxDynamicSharedMemorySize, SM_ATTN);
    cudaFuncSetAttribute(k_proj, cudaFuncAttributeMaxDynamicSharedMemorySize, SM_PROJ);

    k_prep<<<224, 256>>>(x, nw, nb, qkvw, projw);
    k_qkv<<<dim3(64, BB), 256, SM_QKV>>>(x, qkvb);
    k_attn<<<dim3(16, 2, BB), 256, SM_ATTN>>>();
    k_proj<<<dim3(64, BB), 256, SM_PROJ>>>(x, projb, out);
}